// round 13
// baseline (speedup 1.0000x reference)
#include <cuda_runtime.h>
#include <math.h>

// GaussianVoxelizer: 100x100x8 voxels, 128 gaussians, 16 features.
// Voxel centers analytic: coord = (i + 0.5f)*0.8f + lo, lo = (-40,-40,-1).
// 2500 CTAs x 32 threads (warp == CTA, no __syncthreads ever).
// Warp owns 32 CONSECUTIVE voxels: x fixed, y in [wy,wy+4), z in [0,8).
// Params staged to shared with coalesced float4 loads (warp-local, __syncwarp),
// cull reads conflict-free LDS, survivors read uniform LDS broadcasts,
// feature output transposed through padded shared for coalesced STG.128.
#define NVOX 80000
#define NG   128
#define NF   16
#define TPB  32

__global__ __launch_bounds__(TPB) void gv_kernel(const float* __restrict__ means,
                                                 const float* __restrict__ opac,
                                                 const float* __restrict__ feats,
                                                 const float* __restrict__ covs,
                                                 float* __restrict__ out) {
    const unsigned FULL = 0xffffffffu;
    __shared__ float4 s4[416];          // means 96 | opac 32 | covs 288 (float4s)
    __shared__ float  st[NF * 33];      // padded feature transpose buffer

    float* s_means = (float*)s4;        // [0..383]
    float* s_opac  = (float*)s4 + 384;  // [384..511]
    float* s_cov   = (float*)s4 + 512;  // [512..1663]

    int lane = threadIdx.x;

    // ---- Coalesced staging: 13 LDG.128 -> STS.128 ----
    {
        const float4* m4 = (const float4*)means;  // 96
        const float4* o4 = (const float4*)opac;   // 32
        const float4* c4 = (const float4*)covs;   // 288
#pragma unroll
        for (int t = 0; t < 3; t++) s4[lane + 32 * t] = m4[lane + 32 * t];
        s4[96 + lane] = o4[lane];
#pragma unroll
        for (int t = 0; t < 9; t++) s4[128 + lane + 32 * t] = c4[lane + 32 * t];
    }

    // Brick geometry: blockIdx -> (x, y-tile). 100 x * 25 ytiles = 2500.
    int x  = blockIdx.x / 25;
    int wy = (blockIdx.x - x * 25) * 4;
    int y  = wy + (lane >> 3);
    int z  = lane & 7;
    int n0 = x * 800 + wy * 8;          // warp's first voxel; lane voxel = n0+lane

    float px = ((float)x + 0.5f) * 0.8f + (-40.0f);
    float py = ((float)y + 0.5f) * 0.8f + (-40.0f);
    float pz = ((float)z + 0.5f) * 0.8f + (-1.0f);

    // Warp AABB over voxel centers (x degenerate).
    float bxc   = px;                    // bxmin == bxmax
    float bymin = ((float)wy + 0.5f) * 0.8f - 40.0f;
    float bymax = ((float)wy + 3.5f) * 0.8f - 40.0f;
    const float bzmin = 0.5f * 0.8f - 1.0f;
    const float bzmax = 7.5f * 0.8f - 1.0f;

    __syncwarp();

    float cnt = 0.0f, sumd = 0.0f;
    float sumf[NF];
#pragma unroll
    for (int k = 0; k < NF; k++) sumf[k] = 0.0f;

#pragma unroll
    for (int j = 0; j < 4; j++) {
        int gc = lane + 32 * j;
        // Conflict-free LDS: strides 3 and 9 are odd -> distinct banks per lane.
        float mx = s_means[gc * 3 + 0];
        float my = s_means[gc * 3 + 1];
        float mz = s_means[gc * 3 + 2];
        float ax = s_cov[gc * 9 + 0];
        float ay = s_cov[gc * 9 + 4];
        float az = s_cov[gc * 9 + 8];
        // Sqrt-free conservative cull: dist(mean, brick)^2 <= 4*C_kk per axis.
        float tx = fmaxf(fabsf(bxc - mx), 0.0f);
        float ty = fmaxf(fmaxf(bymin - my, my - bymax), 0.0f);
        float tz = fmaxf(fmaxf(bzmin - mz, mz - bzmax), 0.0f);
        bool keep = (tx * tx <= 4.0f * ax + 1e-5f) &
                    (ty * ty <= 4.0f * ay + 1e-5f) &
                    (tz * tz <= 4.0f * az + 1e-5f);
        unsigned m = __ballot_sync(FULL, keep);

        while (m) {
            int src = __ffs(m) - 1;
            m &= m - 1;
            int g = src + 32 * j;

            // Feature prefetch (uniform -> L2 broadcast), overlaps maha chain.
            const float4* fgp = (const float4*)(feats + g * NF);
            float4 f0 = __ldg(fgp + 0);
            float4 f1 = __ldg(fgp + 1);
            float4 f2 = __ldg(fgp + 2);
            float4 f3 = __ldg(fgp + 3);

            // Uniform LDS broadcasts (1 wavefront each).
            const float* C = s_cov + g * 9;
            float a = C[0], b = C[1], c = C[2];
            float d = C[4], e = C[5], f = C[8];
            float gx = s_means[g * 3 + 0];
            float gy = s_means[g * 3 + 1];
            float gz = s_means[g * 3 + 2];
            float op = s_opac[g];

            // Symmetric 3x3 inverse (~25 flops, redundant per lane).
            float c00 = d * f - e * e;
            float c01 = c * e - b * f;
            float c02 = b * e - c * d;
            float det = a * c00 + b * c01 + c * c02;
            float id  = 1.0f / det;

            float dx = px - gx, dy = py - gy, dz = pz - gz;
            float maha =          (c00 * id) * (dx * dx);
            maha = fmaf((a * f - c * c) * id, dy * dy, maha);
            maha = fmaf((a * d - b * b) * id, dz * dz, maha);
            maha = fmaf(2.0f * c01 * id,      dx * dy, maha);
            maha = fmaf(2.0f * c02 * id,      dx * dz, maha);
            maha = fmaf(2.0f * (b * c - a * e) * id, dy * dz, maha);

            // Branchless: miss contributes exactly zero.
            bool hit = (maha <= 4.0f);
            float wgt = hit ? __expf(-0.5f * maha) : 0.0f;
            cnt += hit ? 1.0f : 0.0f;
            float s = op * wgt;
            sumd += s;
            sumf[0]  = fmaf(s, f0.x, sumf[0]);
            sumf[1]  = fmaf(s, f0.y, sumf[1]);
            sumf[2]  = fmaf(s, f0.z, sumf[2]);
            sumf[3]  = fmaf(s, f0.w, sumf[3]);
            sumf[4]  = fmaf(s, f1.x, sumf[4]);
            sumf[5]  = fmaf(s, f1.y, sumf[5]);
            sumf[6]  = fmaf(s, f1.z, sumf[6]);
            sumf[7]  = fmaf(s, f1.w, sumf[7]);
            sumf[8]  = fmaf(s, f2.x, sumf[8]);
            sumf[9]  = fmaf(s, f2.y, sumf[9]);
            sumf[10] = fmaf(s, f2.z, sumf[10]);
            sumf[11] = fmaf(s, f2.w, sumf[11]);
            sumf[12] = fmaf(s, f3.x, sumf[12]);
            sumf[13] = fmaf(s, f3.y, sumf[13]);
            sumf[14] = fmaf(s, f3.z, sumf[14]);
            sumf[15] = fmaf(s, f3.w, sumf[15]);
        }
    }

    float inv = (cnt > 0.0f) ? (1.0f / cnt) : 0.0f;

    // Density: 32 consecutive floats, fully coalesced.
    out[n0 + lane] = sumd * inv;

    // Features: transpose through padded shared -> 4 coalesced STG.128.
    // st layout: st[k*33 + v] = feature k of voxel v. STS banks (k+v)%32: all
    // lanes distinct per k -> conflict-free.
#pragma unroll
    for (int k = 0; k < NF; k++) st[k * 33 + lane] = sumf[k] * inv;
    __syncwarp();

    float* fbase = out + NVOX + (size_t)n0 * NF;
#pragma unroll
    for (int q = 0; q < 4; q++) {
        // Output float4 #(q*32 + lane) of the warp's 2KB region.
        int v  = 8 * q + (lane >> 2);        // voxel within warp
        int k0 = (lane & 3) * 4;             // first feature component
        float4 val = make_float4(st[(k0 + 0) * 33 + v],
                                 st[(k0 + 1) * 33 + v],
                                 st[(k0 + 2) * 33 + v],
                                 st[(k0 + 3) * 33 + v]);
        ((float4*)fbase)[q * 32 + lane] = val;
    }
}

extern "C" void kernel_launch(void* const* d_in, const int* in_sizes, int n_in,
                              void* d_out, int out_size) {
    // d_in[0] = grid_coords (unused: analytic), [1]=means, [2]=opac, [3]=feats, [4]=covs
    const float* means = (const float*)d_in[1];
    const float* opac  = (const float*)d_in[2];
    const float* feats = (const float*)d_in[3];
    const float* covs  = (const float*)d_in[4];
    float* out = (float*)d_out;

    gv_kernel<<<2500, TPB>>>(means, opac, feats, covs, out);
}

// round 14
// speedup vs baseline: 1.4159x; 1.4159x over previous
#include <cuda_runtime.h>
#include <math.h>

// GaussianVoxelizer: 100x100x8 voxels, 128 gaussians, 16 features.
// Voxel centers analytic: coord = (i + 0.5f)*0.8f + lo, lo = (-40,-40,-1).
// Warp-per-block: 2500 blocks x 32 threads; each warp owns a 2x2x8 brick
// (1 voxel/lane). No shared memory, no barriers. All 4 cull ballots hoisted
// ahead of the survivor loops; branchless survivor body with feature prefetch.
#define NVOX 80000
#define NG   128
#define NF   16
#define TPB  32

__global__ __launch_bounds__(TPB, 32) void gv_kernel(const float* __restrict__ means,
                                                     const float* __restrict__ opac,
                                                     const float* __restrict__ feats,
                                                     const float* __restrict__ covs,
                                                     float* __restrict__ out) {
    const unsigned FULL = 0xffffffffu;
    int lane = threadIdx.x;

    // Block -> 2x2 xy brick over a 50x50 brick grid, full z.
    int xt = blockIdx.x / 50;
    int yt = blockIdx.x - xt * 50;
    int wx = xt * 2;
    int wy = yt * 2;
    int lxy = lane >> 3;                  // 0..3
    int x = wx + (lxy >> 1);
    int y = wy + (lxy & 1);
    int z = lane & 7;

    float px = ((float)x + 0.5f) * 0.8f + (-40.0f);
    float py = ((float)y + 0.5f) * 0.8f + (-40.0f);
    float pz = ((float)z + 0.5f) * 0.8f + (-1.0f);

    // Brick AABB over voxel centers.
    float bxmin = ((float)wx + 0.5f) * 0.8f - 40.0f;
    float bxmax = ((float)wx + 1.5f) * 0.8f - 40.0f;
    float bymin = ((float)wy + 0.5f) * 0.8f - 40.0f;
    float bymax = ((float)wy + 1.5f) * 0.8f - 40.0f;
    const float bzmin = 0.5f * 0.8f - 1.0f;
    const float bzmax = 7.5f * 0.8f - 1.0f;

    // Lane owns gaussians g = lane + 32j, j=0..3; raw params in registers.
    float ca[4], cb[4], cc[4], cd[4], ce[4], cf[4];
    float gmx[4], gmy[4], gmz[4], gop[4];
#pragma unroll
    for (int j = 0; j < 4; j++) {
        int g = lane + 32 * j;
        const float* C = covs + g * 9;
        ca[j] = C[0]; cb[j] = C[1]; cc[j] = C[2];
        cd[j] = C[4]; ce[j] = C[5]; cf[j] = C[8];
        gmx[j] = means[g * 3 + 0];
        gmy[j] = means[g * 3 + 1];
        gmz[j] = means[g * 3 + 2];
        gop[j] = opac[g];
    }

    // Hoisted cull: all 4 ballots issue before any survivor work, so the first
    // survivor's feature prefetch starts as early as possible.
    unsigned msk[4];
#pragma unroll
    for (int j = 0; j < 4; j++) {
        // Sqrt-free conservative cull: dist(mean, brick)^2 <= 4*C_kk per axis.
        float tx = fmaxf(fmaxf(bxmin - gmx[j], gmx[j] - bxmax), 0.0f);
        float ty = fmaxf(fmaxf(bymin - gmy[j], gmy[j] - bymax), 0.0f);
        float tz = fmaxf(fmaxf(bzmin - gmz[j], gmz[j] - bzmax), 0.0f);
        bool keep = (tx * tx <= 4.0f * ca[j] + 1e-5f) &
                    (ty * ty <= 4.0f * cd[j] + 1e-5f) &
                    (tz * tz <= 4.0f * cf[j] + 1e-5f);
        msk[j] = __ballot_sync(FULL, keep);
    }

    float cnt = 0.0f, sumd = 0.0f;
    float sumf[NF];
#pragma unroll
    for (int k = 0; k < NF; k++) sumf[k] = 0.0f;

#pragma unroll
    for (int j = 0; j < 4; j++) {
        unsigned m = msk[j];
        while (m) {
            int src = __ffs(m) - 1;
            m &= m - 1;
            int g = src + 32 * j;

            // Prefetch features NOW (uniform -> L2 broadcast); latency overlaps
            // the shfl/inverse/maha chain below.
            const float4* fgp = (const float4*)(feats + g * NF);
            float4 f0 = __ldg(fgp + 0);
            float4 f1 = __ldg(fgp + 1);
            float4 f2 = __ldg(fgp + 2);
            float4 f3 = __ldg(fgp + 3);

            // Broadcast raw params from owner lane.
            float a  = __shfl_sync(FULL, ca[j],  src);
            float b  = __shfl_sync(FULL, cb[j],  src);
            float c  = __shfl_sync(FULL, cc[j],  src);
            float d  = __shfl_sync(FULL, cd[j],  src);
            float e  = __shfl_sync(FULL, ce[j],  src);
            float f  = __shfl_sync(FULL, cf[j],  src);
            float mx = __shfl_sync(FULL, gmx[j], src);
            float my = __shfl_sync(FULL, gmy[j], src);
            float mz = __shfl_sync(FULL, gmz[j], src);
            float op = __shfl_sync(FULL, gop[j], src);

            // Redundant per-lane symmetric 3x3 inverse (~25 flops).
            float c00 = d * f - e * e;
            float c01 = c * e - b * f;
            float c02 = b * e - c * d;
            float det = a * c00 + b * c01 + c * c02;
            float id  = 1.0f / det;

            float dx = px - mx, dy = py - my, dz = pz - mz;
            float maha =          (c00 * id) * (dx * dx);
            maha = fmaf((a * f - c * c) * id, dy * dy, maha);
            maha = fmaf((a * d - b * b) * id, dz * dz, maha);
            maha = fmaf(2.0f * c01 * id,      dx * dy, maha);
            maha = fmaf(2.0f * c02 * id,      dx * dz, maha);
            maha = fmaf(2.0f * (b * c - a * e) * id, dy * dz, maha);

            // Branchless: miss contributes exactly zero.
            bool hit = (maha <= 4.0f);
            float wgt = hit ? __expf(-0.5f * maha) : 0.0f;
            cnt += hit ? 1.0f : 0.0f;
            float s = op * wgt;
            sumd += s;
            sumf[0]  = fmaf(s, f0.x, sumf[0]);
            sumf[1]  = fmaf(s, f0.y, sumf[1]);
            sumf[2]  = fmaf(s, f0.z, sumf[2]);
            sumf[3]  = fmaf(s, f0.w, sumf[3]);
            sumf[4]  = fmaf(s, f1.x, sumf[4]);
            sumf[5]  = fmaf(s, f1.y, sumf[5]);
            sumf[6]  = fmaf(s, f1.z, sumf[6]);
            sumf[7]  = fmaf(s, f1.w, sumf[7]);
            sumf[8]  = fmaf(s, f2.x, sumf[8]);
            sumf[9]  = fmaf(s, f2.y, sumf[9]);
            sumf[10] = fmaf(s, f2.z, sumf[10]);
            sumf[11] = fmaf(s, f2.w, sumf[11]);
            sumf[12] = fmaf(s, f3.x, sumf[12]);
            sumf[13] = fmaf(s, f3.y, sumf[13]);
            sumf[14] = fmaf(s, f3.z, sumf[14]);
            sumf[15] = fmaf(s, f3.w, sumf[15]);
        }
    }

    int n = (x * 100 + y) * 8 + z;
    float inv = (cnt > 0.0f) ? (1.0f / cnt) : 0.0f;
    out[n] = sumd * inv;
    float4* fo = (float4*)(out + NVOX + (size_t)n * NF);
#pragma unroll
    for (int q = 0; q < 4; q++)
        fo[q] = make_float4(sumf[q*4+0]*inv, sumf[q*4+1]*inv,
                            sumf[q*4+2]*inv, sumf[q*4+3]*inv);
}

extern "C" void kernel_launch(void* const* d_in, const int* in_sizes, int n_in,
                              void* d_out, int out_size) {
    // d_in[0] = grid_coords (unused: analytic), [1]=means, [2]=opac, [3]=feats, [4]=covs
    const float* means = (const float*)d_in[1];
    const float* opac  = (const float*)d_in[2];
    const float* feats = (const float*)d_in[3];
    const float* covs  = (const float*)d_in[4];
    float* out = (float*)d_out;

    gv_kernel<<<2500, TPB>>>(means, opac, feats, covs, out);
}

// round 15
// speedup vs baseline: 1.7022x; 1.2022x over previous
#include <cuda_runtime.h>
#include <math.h>

// GaussianVoxelizer: 100x100x8 voxels, 128 gaussians, 16 features.
// Voxel centers analytic: coord = (i + 0.5f)*0.8f + lo, lo = (-40,-40,-1).
// Warp-per-block: 2500 blocks x 32 threads; each warp owns a 2x2x8 brick
// (1 voxel/lane). No shared memory, no barriers, no register caps.
// Per-lane loads limited to cull data (mean, diag-cov, opac); off-diagonal
// covariances + features fetched uniformly (__ldg broadcast) per survivor,
// prefetched ahead of the shfl/inverse/maha chain. Branchless survivor body.
#define NVOX 80000
#define NG   128
#define NF   16
#define TPB  32

__global__ __launch_bounds__(TPB) void gv_kernel(const float* __restrict__ means,
                                                 const float* __restrict__ opac,
                                                 const float* __restrict__ feats,
                                                 const float* __restrict__ covs,
                                                 float* __restrict__ out) {
    const unsigned FULL = 0xffffffffu;
    int lane = threadIdx.x;

    // Block -> 2x2 xy brick over a 50x50 brick grid, full z.
    int xt = blockIdx.x / 50;
    int yt = blockIdx.x - xt * 50;
    int wx = xt * 2;
    int wy = yt * 2;
    int lxy = lane >> 3;                  // 0..3
    int x = wx + (lxy >> 1);
    int y = wy + (lxy & 1);
    int z = lane & 7;

    float px = ((float)x + 0.5f) * 0.8f + (-40.0f);
    float py = ((float)y + 0.5f) * 0.8f + (-40.0f);
    float pz = ((float)z + 0.5f) * 0.8f + (-1.0f);

    // Brick AABB over voxel centers.
    float bxmin = ((float)wx + 0.5f) * 0.8f - 40.0f;
    float bxmax = ((float)wx + 1.5f) * 0.8f - 40.0f;
    float bymin = ((float)wy + 0.5f) * 0.8f - 40.0f;
    float bymax = ((float)wy + 1.5f) * 0.8f - 40.0f;
    const float bzmin = 0.5f * 0.8f - 1.0f;
    const float bzmax = 7.5f * 0.8f - 1.0f;

    // Lane owns gaussians g = lane + 32j: cull params only (7 loads per j).
    float gmx[4], gmy[4], gmz[4], gop[4];
    float cxx[4], cyy[4], czz[4];
#pragma unroll
    for (int j = 0; j < 4; j++) {
        int g = lane + 32 * j;
        gmx[j] = means[g * 3 + 0];
        gmy[j] = means[g * 3 + 1];
        gmz[j] = means[g * 3 + 2];
        gop[j] = opac[g];
        cxx[j] = covs[g * 9 + 0];
        cyy[j] = covs[g * 9 + 4];
        czz[j] = covs[g * 9 + 8];
    }

    // Hoisted cull: all 4 ballots before any survivor work.
    unsigned msk[4];
#pragma unroll
    for (int j = 0; j < 4; j++) {
        // Sqrt-free conservative cull: dist(mean, brick)^2 <= 4*C_kk per axis.
        float tx = fmaxf(fmaxf(bxmin - gmx[j], gmx[j] - bxmax), 0.0f);
        float ty = fmaxf(fmaxf(bymin - gmy[j], gmy[j] - bymax), 0.0f);
        float tz = fmaxf(fmaxf(bzmin - gmz[j], gmz[j] - bzmax), 0.0f);
        bool keep = (tx * tx <= 4.0f * cxx[j] + 1e-5f) &
                    (ty * ty <= 4.0f * cyy[j] + 1e-5f) &
                    (tz * tz <= 4.0f * czz[j] + 1e-5f);
        msk[j] = __ballot_sync(FULL, keep);
    }

    float cnt = 0.0f, sumd = 0.0f;
    float sumf[NF];
#pragma unroll
    for (int k = 0; k < NF; k++) sumf[k] = 0.0f;

#pragma unroll
    for (int j = 0; j < 4; j++) {
        unsigned m = msk[j];
        while (m) {
            int src = __ffs(m) - 1;
            m &= m - 1;
            int g = src + 32 * j;

            // Uniform prefetches (L2 broadcast): off-diag cov + features.
            // Latency overlaps the shfl/inverse/maha chain below.
            float b = __ldg(covs + g * 9 + 1);
            float c = __ldg(covs + g * 9 + 2);
            float e = __ldg(covs + g * 9 + 5);
            const float4* fgp = (const float4*)(feats + g * NF);
            float4 f0 = __ldg(fgp + 0);
            float4 f1 = __ldg(fgp + 1);
            float4 f2 = __ldg(fgp + 2);
            float4 f3 = __ldg(fgp + 3);

            // Broadcast owner-lane registers (7 shfls).
            float a  = __shfl_sync(FULL, cxx[j], src);
            float d  = __shfl_sync(FULL, cyy[j], src);
            float f  = __shfl_sync(FULL, czz[j], src);
            float mx = __shfl_sync(FULL, gmx[j], src);
            float my = __shfl_sync(FULL, gmy[j], src);
            float mz = __shfl_sync(FULL, gmz[j], src);
            float op = __shfl_sync(FULL, gop[j], src);

            // Redundant per-lane symmetric 3x3 inverse (~25 flops).
            float c00 = d * f - e * e;
            float c01 = c * e - b * f;
            float c02 = b * e - c * d;
            float det = a * c00 + b * c01 + c * c02;
            float id  = 1.0f / det;

            float dx = px - mx, dy = py - my, dz = pz - mz;
            float maha =          (c00 * id) * (dx * dx);
            maha = fmaf((a * f - c * c) * id, dy * dy, maha);
            maha = fmaf((a * d - b * b) * id, dz * dz, maha);
            maha = fmaf(2.0f * c01 * id,      dx * dy, maha);
            maha = fmaf(2.0f * c02 * id,      dx * dz, maha);
            maha = fmaf(2.0f * (b * c - a * e) * id, dy * dz, maha);

            // Branchless: miss contributes exactly zero.
            bool hit = (maha <= 4.0f);
            float wgt = hit ? __expf(-0.5f * maha) : 0.0f;
            cnt += hit ? 1.0f : 0.0f;
            float s = op * wgt;
            sumd += s;
            sumf[0]  = fmaf(s, f0.x, sumf[0]);
            sumf[1]  = fmaf(s, f0.y, sumf[1]);
            sumf[2]  = fmaf(s, f0.z, sumf[2]);
            sumf[3]  = fmaf(s, f0.w, sumf[3]);
            sumf[4]  = fmaf(s, f1.x, sumf[4]);
            sumf[5]  = fmaf(s, f1.y, sumf[5]);
            sumf[6]  = fmaf(s, f1.z, sumf[6]);
            sumf[7]  = fmaf(s, f1.w, sumf[7]);
            sumf[8]  = fmaf(s, f2.x, sumf[8]);
            sumf[9]  = fmaf(s, f2.y, sumf[9]);
            sumf[10] = fmaf(s, f2.z, sumf[10]);
            sumf[11] = fmaf(s, f2.w, sumf[11]);
            sumf[12] = fmaf(s, f3.x, sumf[12]);
            sumf[13] = fmaf(s, f3.y, sumf[13]);
            sumf[14] = fmaf(s, f3.z, sumf[14]);
            sumf[15] = fmaf(s, f3.w, sumf[15]);
        }
    }

    int n = (x * 100 + y) * 8 + z;
    float inv = (cnt > 0.0f) ? (1.0f / cnt) : 0.0f;
    out[n] = sumd * inv;
    float4* fo = (float4*)(out + NVOX + (size_t)n * NF);
#pragma unroll
    for (int q = 0; q < 4; q++)
        fo[q] = make_float4(sumf[q*4+0]*inv, sumf[q*4+1]*inv,
                            sumf[q*4+2]*inv, sumf[q*4+3]*inv);
}

extern "C" void kernel_launch(void* const* d_in, const int* in_sizes, int n_in,
                              void* d_out, int out_size) {
    // d_in[0] = grid_coords (unused: analytic), [1]=means, [2]=opac, [3]=feats, [4]=covs
    const float* means = (const float*)d_in[1];
    const float* opac  = (const float*)d_in[2];
    const float* feats = (const float*)d_in[3];
    const float* covs  = (const float*)d_in[4];
    float* out = (float*)d_out;

    gv_kernel<<<2500, TPB>>>(means, opac, feats, covs, out);
}